// round 1
// baseline (speedup 1.0000x reference)
#include <cuda_runtime.h>
#include <math.h>

#define B 128

// ping-pong activation buffers (device globals: no allocation allowed)
__device__ float g_h0[B * 1024];
__device__ float g_h1[B * 1024];

__device__ __forceinline__ float ex2f(float x) {
    float y;
    asm("ex2.approx.f32 %0, %1;" : "=f"(y) : "f"(x));
    return y;
}

// identity on [0,1], slope 0.1 outside
__device__ __forceinline__ float leaky_clamp01(float w) {
    float r = w;
    if (w < 0.0f)      r = 0.1f * w;
    else if (w > 1.0f) r = 1.0f + 0.1f * (w - 1.0f);
    return r;
}

// h0 = concat(x, 1-x) along feature dim
__global__ void init_h_kernel(const float* __restrict__ x) {
    int i = blockIdx.x * blockDim.x + threadIdx.x;
    if (i < B * 512) {
        int b = i >> 9, c = i & 511;
        float v = x[i];
        g_h0[b * 1024 + c]       = v;
        g_h0[b * 1024 + 512 + c] = 1.0f - v;
    }
}

// One OR-gate layer (+ trailing inversion):
//   out[b,o] = 1 - (sum_i e^(tau*z) * z) / (sum_i e^(tau*z)),  z = h[b,i]*leaky_clamp(W[o,i])
// Using cs = tau*log2e, ch = cs*h:  arg = ch*aw;  e = 2^arg;
//   num = sum e*arg = cs * sum(e*z);  den = sum e;  out = 1 - num/(cs*den)
template <int IN, int BT, int OT, int KC>
__global__ void layer_kernel(const float* __restrict__ h,
                             const float* __restrict__ W,
                             const float* __restrict__ taup,
                             float tau_floor,
                             float* __restrict__ out,
                             int out_dim) {
    constexpr int T = (BT / 2) * (OT / 2);   // threads per block (2x2 micro-tile)
    __shared__ float ch[BT][KC + 1];         // +1 pad: conflict-free column reads
    __shared__ float aw[OT][KC + 1];

    const int tid   = threadIdx.x;
    const int obase = blockIdx.x * OT;
    const int bbase = blockIdx.y * BT;
    const int bq    = tid % (BT / 2);
    const int oq    = tid / (BT / 2);

    const float ta  = *taup;
    const float tau = tau_floor + (ta >= 0.0f ? ta : 0.05f * ta); // leaky_relu(tau_adder)
    const float cs  = tau * 1.4426950408889634f;                  // tau * log2(e)

    float n00 = 0.f, n01 = 0.f, n10 = 0.f, n11 = 0.f;
    float d00 = 0.f, d01 = 0.f, d10 = 0.f, d11 = 0.f;

    for (int k0 = 0; k0 < IN; k0 += KC) {
        __syncthreads();
        // stage cs-scaled activations
        #pragma unroll
        for (int idx = tid; idx < BT * KC; idx += T) {
            int bb = idx / KC, kk = idx - bb * KC;
            ch[bb][kk] = h[(bbase + bb) * IN + k0 + kk] * cs;
        }
        // stage leaky-clamped weights
        #pragma unroll
        for (int idx = tid; idx < OT * KC; idx += T) {
            int oo = idx / KC, kk = idx - oo * KC;
            aw[oo][kk] = leaky_clamp01(W[(obase + oo) * IN + k0 + kk]);
        }
        __syncthreads();

        #pragma unroll 16
        for (int k = 0; k < KC; k++) {
            float c0 = ch[bq][k];
            float c1 = ch[bq + BT / 2][k];
            float a0 = aw[oq][k];
            float a1 = aw[oq + OT / 2][k];
            float z0 = c0 * a0, z1 = c0 * a1, z2 = c1 * a0, z3 = c1 * a1;
            float e0 = ex2f(z0), e1 = ex2f(z1), e2 = ex2f(z2), e3 = ex2f(z3);
            d00 += e0; n00 = fmaf(e0, z0, n00);
            d01 += e1; n01 = fmaf(e1, z1, n01);
            d10 += e2; n10 = fmaf(e2, z2, n10);
            d11 += e3; n11 = fmaf(e3, z3, n11);
        }
    }

    const float invc = 1.0f / cs;
    const int b0 = bbase + bq, b1 = b0 + BT / 2;
    const int o0 = obase + oq, o1 = o0 + OT / 2;
    out[b0 * out_dim + o0] = 1.0f - (n00 / d00) * invc;
    out[b0 * out_dim + o1] = 1.0f - (n01 / d01) * invc;
    out[b1 * out_dim + o0] = 1.0f - (n10 / d10) * invc;
    out[b1 * out_dim + o1] = 1.0f - (n11 / d11) * invc;
}

extern "C" void kernel_launch(void* const* d_in, const int* in_sizes, int n_in,
                              void* d_out, int out_size) {
    // metadata order: x, W0, tau0, W1, tau1, W2, tau2, W3, tau3
    const float* x  = (const float*)d_in[0];
    const float* W0 = (const float*)d_in[1];
    const float* t0 = (const float*)d_in[2];
    const float* W1 = (const float*)d_in[3];
    const float* t1 = (const float*)d_in[4];
    const float* W2 = (const float*)d_in[5];
    const float* t2 = (const float*)d_in[6];
    const float* W3 = (const float*)d_in[7];
    const float* t3 = (const float*)d_in[8];
    float* out = (float*)d_out;

    float *h0, *h1;
    cudaGetSymbolAddress((void**)&h0, g_h0);
    cudaGetSymbolAddress((void**)&h1, g_h1);

    // tau_floor = log(in-1) + log(0.95) - log(0.05)
    const float L19 = 2.9444389791664403f;  // log(0.95/0.05)
    const float tf0 = logf(1023.0f) + L19;
    const float tf1 = logf(1023.0f) + L19;
    const float tf2 = logf(511.0f)  + L19;
    const float tf3 = logf(255.0f)  + L19;

    init_h_kernel<<<(B * 512 + 255) / 256, 256>>>(x);

    // L0: 1024 -> 1024   (256 blocks x 128 thr)
    layer_kernel<1024, 32, 16, 64><<<dim3(1024 / 16, B / 32), 128>>>(h0, W0, t0, tf0, h1, 1024);
    // L1: 1024 -> 512    (256 blocks x 64 thr)
    layer_kernel<1024, 16, 16, 64><<<dim3(512 / 16, B / 16), 64>>>(h1, W1, t1, tf1, h0, 512);
    // L2: 512 -> 256     (256 blocks x 32 thr)
    layer_kernel<512, 16, 8, 64><<<dim3(256 / 8, B / 16), 32>>>(h0, W2, t2, tf2, h1, 256);
    // L3: 256 -> 128     (128 blocks x 32 thr)
    layer_kernel<256, 16, 8, 64><<<dim3(128 / 8, B / 16), 32>>>(h1, W3, t3, tf3, out, 128);
}

// round 2
// speedup vs baseline: 2.2838x; 2.2838x over previous
#include <cuda_runtime.h>
#include <math.h>

#define B 128

// ping-pong activation buffers (device globals: no allocation allowed)
__device__ float g_h1[B * 1024];
__device__ float g_h2[B * 512];
__device__ float g_h3[B * 256];

__device__ __forceinline__ float ex2f(float x) {
    float y;
    asm("ex2.approx.f32 %0, %1;" : "=f"(y) : "f"(x));
    return y;
}

// identity on [0,1], slope 0.1 outside
__device__ __forceinline__ float leaky_clamp01(float w) {
    float r = w;
    if (w < 0.0f)      r = 0.1f * w;
    else if (w > 1.0f) r = 1.0f + 0.1f * (w - 1.0f);
    return r;
}

// One OR-gate layer (+ trailing inversion):
//   out[b,o] = 1 - (sum_i e^(tau*z) * z) / (sum_i e^(tau*z)),  z = h[b,i]*leaky_clamp(W[o,i])
// With cs = tau*log2e and ch = cs*h:  arg = ch*aw; e = 2^arg;
//   num = sum e*arg = cs * sum(e*z); den = sum e; out = 1 - (num/den)/cs
//
// OPT = outputs per thread (1 or 2). Threads = BT*OT/OPT.
// CAT = layer-0 mode: h is x[B][IN/2], staged as concat(x, 1-x).
template <int IN, int BT, int OT, int OPT, int KC, bool CAT>
__global__ void layer_kernel(const float* __restrict__ h,
                             const float* __restrict__ W,
                             const float* __restrict__ taup,
                             float tau_floor,
                             float* __restrict__ out,
                             int out_dim) {
    constexpr int T  = BT * (OT / OPT);
    constexpr int OH = OT / OPT;
    __shared__ float ch[BT][KC + 1];   // +1 pad: conflict-free column reads
    __shared__ float aw[OT][KC + 1];

    const int tid   = threadIdx.x;
    const int obase = blockIdx.x * OT;
    const int bbase = blockIdx.y * BT;
    const int bq    = tid % BT;
    const int oh    = tid / BT;

    const float ta  = *taup;
    const float tau = tau_floor + (ta >= 0.0f ? ta : 0.05f * ta); // leaky_relu
    const float cs  = tau * 1.4426950408889634f;                  // tau * log2(e)

    float num[OPT], den[OPT];
    #pragma unroll
    for (int j = 0; j < OPT; j++) { num[j] = 0.0f; den[j] = 0.0f; }

    for (int k0 = 0; k0 < IN; k0 += KC) {
        __syncthreads();
        // stage cs-scaled activations (fused concat(x,1-x) for layer 0)
        #pragma unroll
        for (int idx = tid; idx < BT * KC; idx += T) {
            int bb = idx / KC, kk = idx - bb * KC;
            int gk = k0 + kk;
            float v;
            if (CAT) {
                v = h[(bbase + bb) * (IN / 2) + (gk & (IN / 2 - 1))];
                if (gk >= IN / 2) v = 1.0f - v;
            } else {
                v = h[(bbase + bb) * IN + gk];
            }
            ch[bb][kk] = v * cs;
        }
        // stage leaky-clamped weights
        #pragma unroll
        for (int idx = tid; idx < OT * KC; idx += T) {
            int oo = idx / KC, kk = idx - oo * KC;
            aw[oo][kk] = leaky_clamp01(W[(obase + oo) * IN + k0 + kk]);
        }
        __syncthreads();

        #pragma unroll 8
        for (int k = 0; k < KC; k++) {
            float c = ch[bq][k];
            #pragma unroll
            for (int j = 0; j < OPT; j++) {
                float z = c * aw[oh + j * OH][k];
                float e = ex2f(z);
                den[j] += e;
                num[j] = fmaf(e, z, num[j]);
            }
        }
    }

    const float invc = 1.0f / cs;
    const int b = bbase + bq;
    #pragma unroll
    for (int j = 0; j < OPT; j++) {
        int o = obase + oh + j * OH;
        out[b * out_dim + o] = 1.0f - (num[j] / den[j]) * invc;
    }
}

extern "C" void kernel_launch(void* const* d_in, const int* in_sizes, int n_in,
                              void* d_out, int out_size) {
    // metadata order: x, W0, tau0, W1, tau1, W2, tau2, W3, tau3
    const float* x  = (const float*)d_in[0];
    const float* W0 = (const float*)d_in[1];
    const float* t0 = (const float*)d_in[2];
    const float* W1 = (const float*)d_in[3];
    const float* t1 = (const float*)d_in[4];
    const float* W2 = (const float*)d_in[5];
    const float* t2 = (const float*)d_in[6];
    const float* W3 = (const float*)d_in[7];
    const float* t3 = (const float*)d_in[8];
    float* out = (float*)d_out;

    float *h1, *h2, *h3;
    cudaGetSymbolAddress((void**)&h1, g_h1);
    cudaGetSymbolAddress((void**)&h2, g_h2);
    cudaGetSymbolAddress((void**)&h3, g_h3);

    // tau_floor = log(in-1) + log(0.95) - log(0.05)
    const float L19 = 2.9444389791664403f;  // log(0.95/0.05)
    const float tf0 = logf(1023.0f) + L19;
    const float tf1 = logf(1023.0f) + L19;
    const float tf2 = logf(511.0f)  + L19;
    const float tf3 = logf(255.0f)  + L19;

    // L0: 1024 -> 1024, fused concat. 256 blocks x 256 thr (2 o/thread)
    layer_kernel<1024, 16, 32, 2, 128, true>
        <<<dim3(1024 / 32, B / 16), 256>>>(x, W0, t0, tf0, h1, 1024);
    // L1: 1024 -> 512. 256 blocks x 128 thr (2 o/thread)
    layer_kernel<1024, 8, 32, 2, 128, false>
        <<<dim3(512 / 32, B / 8), 128>>>(h1, W1, t1, tf1, h2, 512);
    // L2: 512 -> 256. 128 blocks x 256 thr (1 o/thread)
    layer_kernel<512, 16, 16, 1, 128, false>
        <<<dim3(256 / 16, B / 16), 256>>>(h2, W2, t2, tf2, h3, 256);
    // L3: 256 -> 128. 128 blocks x 128 thr (1 o/thread)
    layer_kernel<256, 8, 16, 1, 128, false>
        <<<dim3(128 / 16, B / 8), 128>>>(h3, W3, t3, tf3, out, 128);
}

// round 4
// speedup vs baseline: 3.6952x; 1.6180x over previous
#include <cuda_runtime.h>
#include <math.h>

#define B 128

// ping-pong activation buffers (device globals: no allocation allowed)
__device__ float g_h1[B * 1024];
__device__ float g_h2[B * 512];
__device__ float g_h3[B * 256];

__device__ __forceinline__ float ex2f(float x) {
    float y;
    asm("ex2.approx.f32 %0, %1;" : "=f"(y) : "f"(x));
    return y;
}

// identity on [0,1], slope 0.1 outside
__device__ __forceinline__ float leaky_clamp01(float w) {
    float r = w;
    if (w < 0.0f)      r = 0.1f * w;
    else if (w > 1.0f) r = 1.0f + 0.1f * (w - 1.0f);
    return r;
}

__device__ __forceinline__ float tau_scale(const float* taup, float tau_floor) {
    float ta  = __ldg(taup);
    float tau = tau_floor + (ta >= 0.0f ? ta : 0.05f * ta);  // leaky_relu
    return tau * 1.4426950408889634f;                        // tau * log2(e)
}

// ============================================================================
// Chunked kernel (big layers, S=1). Thread = one (b,o) output, full K.
// out[b,o] = 1 - (sum_i e^arg * arg)/(cs * sum_i e^arg), arg = cs*h[b,i]*aw[o,i]
// CAT: layer-0 mode, h is x[B][IN/2], staged as concat(x, 1-x) on the fly.
// ============================================================================
template <int IN, int BT, int OT, int KC, bool CAT>
__global__ __launch_bounds__(BT * OT) void layer_chunked(
    const float* __restrict__ h, const float* __restrict__ W,
    const float* __restrict__ taup, float tau_floor,
    float* __restrict__ out, int out_dim) {
    constexpr int T   = BT * OT;
    constexpr int KCP = KC + 1;
    __shared__ float ch[BT * KCP];
    __shared__ float aw[OT * KCP];

    const int tid   = threadIdx.x;
    const int obase = blockIdx.x * OT;
    const int bbase = blockIdx.y * BT;
    const int b     = tid % BT;
    const int o     = tid / BT;

    const float cs = tau_scale(taup, tau_floor);

    float num = 0.0f, den = 0.0f;

    for (int k0 = 0; k0 < IN; k0 += KC) {
        if (k0) __syncthreads();
        // stage activations (float4 LDG, scalar STS into padded rows)
        {
            const bool inv  = CAT && (k0 >= IN / 2);
            const float sc  = inv ? -cs : cs;
            const float off = inv ?  cs : 0.0f;
            const int hk0   = CAT ? (k0 & (IN / 2 - 1)) : k0;
            const int hstr  = CAT ? (IN / 2) : IN;
            #pragma unroll
            for (int i = tid; i < BT * (KC / 4); i += T) {
                int bb = i / (KC / 4), kv = i - bb * (KC / 4);
                float4 v = *(const float4*)&h[(bbase + bb) * hstr + hk0 + kv * 4];
                float* d = &ch[bb * KCP + kv * 4];
                d[0] = fmaf(v.x, sc, off);
                d[1] = fmaf(v.y, sc, off);
                d[2] = fmaf(v.z, sc, off);
                d[3] = fmaf(v.w, sc, off);
            }
        }
        // stage weights
        #pragma unroll
        for (int i = tid; i < OT * (KC / 4); i += T) {
            int oo = i / (KC / 4), kv = i - oo * (KC / 4);
            float4 v = *(const float4*)&W[(obase + oo) * IN + k0 + kv * 4];
            float* d = &aw[oo * KCP + kv * 4];
            d[0] = leaky_clamp01(v.x);
            d[1] = leaky_clamp01(v.y);
            d[2] = leaky_clamp01(v.z);
            d[3] = leaky_clamp01(v.w);
        }
        __syncthreads();

        #pragma unroll 8
        for (int k = 0; k < KC; k++) {
            float z = ch[b * KCP + k] * aw[o * KCP + k];
            float e = ex2f(z);
            den += e;
            num = fmaf(e, z, num);
        }
    }

    out[(bbase + b) * out_dim + obase + o] = 1.0f - (num / den) / cs;
}

// ============================================================================
// Split kernel (small layers). Stage the WHOLE input once; S threads share an
// output, each covering IN/S of K; partials summed via smem (num,den additive).
// ============================================================================
template <int IN, int BT, int OT, int S>
__global__ __launch_bounds__(BT * OT * S) void layer_split(
    const float* __restrict__ h, const float* __restrict__ W,
    const float* __restrict__ taup, float tau_floor,
    float* __restrict__ out, int out_dim) {
    constexpr int T   = BT * OT * S;
    constexpr int G   = BT * OT;     // outputs per block
    constexpr int KR  = IN / S;      // K range per thread
    constexpr int INP = IN + 1;
    __shared__ float ch[BT * INP];
    __shared__ float aw[OT * INP];
    __shared__ float rnum[T], rden[T];

    const int tid   = threadIdx.x;
    const int obase = blockIdx.x * OT;
    const int bbase = blockIdx.y * BT;
    const int idx   = tid & (G - 1);
    const int s     = tid / G;
    const int b     = idx % BT;
    const int o     = idx / BT;

    const float cs = tau_scale(taup, tau_floor);

    // stage full activations + weights
    #pragma unroll
    for (int i = tid; i < BT * (IN / 4); i += T) {
        int bb = i / (IN / 4), kv = i - bb * (IN / 4);
        float4 v = *(const float4*)&h[(bbase + bb) * IN + kv * 4];
        float* d = &ch[bb * INP + kv * 4];
        d[0] = v.x * cs; d[1] = v.y * cs; d[2] = v.z * cs; d[3] = v.w * cs;
    }
    #pragma unroll
    for (int i = tid; i < OT * (IN / 4); i += T) {
        int oo = i / (IN / 4), kv = i - oo * (IN / 4);
        float4 v = *(const float4*)&W[(obase + oo) * IN + kv * 4];
        float* d = &aw[oo * INP + kv * 4];
        d[0] = leaky_clamp01(v.x);
        d[1] = leaky_clamp01(v.y);
        d[2] = leaky_clamp01(v.z);
        d[3] = leaky_clamp01(v.w);
    }
    __syncthreads();

    float num = 0.0f, den = 0.0f;
    const float* cp = &ch[b * INP + s * KR];
    const float* ap = &aw[o * INP + s * KR];
    #pragma unroll 8
    for (int k = 0; k < KR; k++) {
        float z = cp[k] * ap[k];
        float e = ex2f(z);
        den += e;
        num = fmaf(e, z, num);
    }

    rnum[tid] = num;
    rden[tid] = den;
    __syncthreads();
    if (s == 0) {
        #pragma unroll
        for (int ss = 1; ss < S; ss++) {
            num += rnum[idx + ss * G];
            den += rden[idx + ss * G];
        }
        out[(bbase + b) * out_dim + obase + o] = 1.0f - (num / den) / cs;
    }
}

extern "C" void kernel_launch(void* const* d_in, const int* in_sizes, int n_in,
                              void* d_out, int out_size) {
    // metadata order: x, W0, tau0, W1, tau1, W2, tau2, W3, tau3
    const float* x  = (const float*)d_in[0];
    const float* W0 = (const float*)d_in[1];
    const float* t0 = (const float*)d_in[2];
    const float* W1 = (const float*)d_in[3];
    const float* t1 = (const float*)d_in[4];
    const float* W2 = (const float*)d_in[5];
    const float* t2 = (const float*)d_in[6];
    const float* W3 = (const float*)d_in[7];
    const float* t3 = (const float*)d_in[8];
    float* out = (float*)d_out;

    float *h1, *h2, *h3;
    cudaGetSymbolAddress((void**)&h1, g_h1);
    cudaGetSymbolAddress((void**)&h2, g_h2);
    cudaGetSymbolAddress((void**)&h3, g_h3);

    // tau_floor = log(in-1) + log(0.95/0.05)
    const float L19 = 2.9444389791664403f;
    const float tf0 = logf(1023.0f) + L19;
    const float tf1 = logf(1023.0f) + L19;
    const float tf2 = logf(511.0f)  + L19;
    const float tf3 = logf(255.0f)  + L19;

    // L0: 1024->1024, fused concat. 512 blocks x 256 thr (8 warps)
    layer_chunked<1024, 8, 32, 256, true>
        <<<dim3(1024 / 32, B / 8), 256>>>(x, W0, t0, tf0, h1, 1024);
    // L1: 1024->512. 256 blocks x 256 thr
    layer_chunked<1024, 8, 32, 256, false>
        <<<dim3(512 / 32, B / 8), 256>>>(h1, W1, t1, tf1, h2, 512);
    // L2: 512->256, 4-way K split. 512 blocks x 256 thr
    layer_split<512, 8, 8, 4>
        <<<dim3(256 / 8, B / 8), 256>>>(h2, W2, t2, tf2, h3, 256);
    // L3: 256->128, 4-way K split. 256 blocks x 256 thr
    layer_split<256, 8, 8, 4>
        <<<dim3(128 / 8, B / 8), 256>>>(h3, W3, t3, tf3, out, 128);
}

// round 5
// speedup vs baseline: 4.6792x; 1.2663x over previous
#include <cuda_runtime.h>
#include <math.h>

#define B 128

__device__ float g_h1[B * 1024];
__device__ float g_h2[B * 512];
__device__ float g_h3[B * 256];

__device__ __forceinline__ float ex2f(float x) {
    float y;
    asm("ex2.approx.f32 %0, %1;" : "=f"(y) : "f"(x));
    return y;
}

__device__ __forceinline__ float leaky_clamp01(float w) {
    float r = w;
    if (w < 0.0f)      r = 0.1f * w;
    else if (w > 1.0f) r = 1.0f + 0.1f * (w - 1.0f);
    return r;
}

__device__ __forceinline__ float tau_scale(const float* taup, float tau_floor) {
    float ta  = __ldg(taup);
    float tau = tau_floor + (ta >= 0.0f ? ta : 0.05f * ta);  // leaky_relu
    return tau * 1.4426950408889634f;                        // tau * log2(e)
}

// ============================================================================
// Chunked kernel (big layers). Each thread owns 2 outputs (o, o+OT/2) for one
// batch row; float4 smem pipeline; rows padded by 4 floats (alignment + banks).
//   out[b,o] = 1 - (sum e^arg * arg)/(cs * sum e^arg), arg = cs*h[b,i]*aw[o,i]
// CAT: layer-0 mode, h is x[B][IN/2], staged as concat(x, 1-x).
// ============================================================================
template <int IN, int BT, int OT, int KC, bool CAT>
__global__ __launch_bounds__(BT * OT / 2, 4) void layer_chunked(
    const float* __restrict__ h, const float* __restrict__ W,
    const float* __restrict__ taup, float tau_floor,
    float* __restrict__ out, int out_dim) {
    constexpr int T   = BT * OT / 2;
    constexpr int OH  = OT / 2;
    constexpr int KCP = KC + 4;
    __shared__ float ch[BT * KCP];
    __shared__ float aw[OT * KCP];

    const int tid   = threadIdx.x;
    const int obase = blockIdx.x * OT;
    const int bbase = blockIdx.y * BT;
    const int b     = tid % BT;
    const int oh    = tid / BT;

    const float cs = tau_scale(taup, tau_floor);

    float num0 = 0.f, den0 = 0.f, num1 = 0.f, den1 = 0.f;

    for (int k0 = 0; k0 < IN; k0 += KC) {
        if (k0) __syncthreads();
        {   // stage activations (fused concat(x,1-x) for layer 0)
            const bool inv  = CAT && (k0 >= IN / 2);
            const float sc  = inv ? -cs : cs;
            const float off = inv ?  cs : 0.0f;
            const int hk0   = CAT ? (k0 & (IN / 2 - 1)) : k0;
            const int hstr  = CAT ? (IN / 2) : IN;
            #pragma unroll
            for (int i = tid; i < BT * (KC / 4); i += T) {
                int bb = i / (KC / 4), kv = i - bb * (KC / 4);
                float4 v = *(const float4*)&h[(bbase + bb) * hstr + hk0 + kv * 4];
                float4 r;
                r.x = fmaf(v.x, sc, off); r.y = fmaf(v.y, sc, off);
                r.z = fmaf(v.z, sc, off); r.w = fmaf(v.w, sc, off);
                *(float4*)&ch[bb * KCP + kv * 4] = r;
            }
        }
        #pragma unroll
        for (int i = tid; i < OT * (KC / 4); i += T) {
            int oo = i / (KC / 4), kv = i - oo * (KC / 4);
            float4 v = *(const float4*)&W[(obase + oo) * IN + k0 + kv * 4];
            float4 r;
            r.x = leaky_clamp01(v.x); r.y = leaky_clamp01(v.y);
            r.z = leaky_clamp01(v.z); r.w = leaky_clamp01(v.w);
            *(float4*)&aw[oo * KCP + kv * 4] = r;
        }
        __syncthreads();

        const float* cp  = &ch[b * KCP];
        const float* ap0 = &aw[oh * KCP];
        const float* ap1 = &aw[(oh + OH) * KCP];
        #pragma unroll 4
        for (int k = 0; k < KC; k += 4) {
            float4 c  = *(const float4*)&cp[k];
            float4 a0 = *(const float4*)&ap0[k];
            float4 a1 = *(const float4*)&ap1[k];
            float z;
            z = c.x * a0.x; { float e = ex2f(z); den0 += e; num0 = fmaf(e, z, num0); }
            z = c.y * a0.y; { float e = ex2f(z); den0 += e; num0 = fmaf(e, z, num0); }
            z = c.z * a0.z; { float e = ex2f(z); den0 += e; num0 = fmaf(e, z, num0); }
            z = c.w * a0.w; { float e = ex2f(z); den0 += e; num0 = fmaf(e, z, num0); }
            z = c.x * a1.x; { float e = ex2f(z); den1 += e; num1 = fmaf(e, z, num1); }
            z = c.y * a1.y; { float e = ex2f(z); den1 += e; num1 = fmaf(e, z, num1); }
            z = c.z * a1.z; { float e = ex2f(z); den1 += e; num1 = fmaf(e, z, num1); }
            z = c.w * a1.w; { float e = ex2f(z); den1 += e; num1 = fmaf(e, z, num1); }
        }
    }

    const int bo = (bbase + b) * out_dim + obase + oh;
    out[bo]      = 1.0f - (num0 / den0) / cs;
    out[bo + OH] = 1.0f - (num1 / den1) / cs;
}

// ============================================================================
// Split kernel (small layers). Whole input staged once; S threads per output,
// each covering IN/S of K; partials (num, den additive) reduced via smem.
// ============================================================================
template <int IN, int BT, int OT, int S>
__global__ __launch_bounds__(BT * OT * S) void layer_split(
    const float* __restrict__ h, const float* __restrict__ W,
    const float* __restrict__ taup, float tau_floor,
    float* __restrict__ out, int out_dim) {
    constexpr int T   = BT * OT * S;
    constexpr int G   = BT * OT;
    constexpr int KR  = IN / S;
    constexpr int INP = IN + 4;
    __shared__ float ch[BT * INP];
    __shared__ float aw[OT * INP];
    __shared__ float rnum[T], rden[T];

    const int tid   = threadIdx.x;
    const int obase = blockIdx.x * OT;
    const int bbase = blockIdx.y * BT;
    const int idx   = tid & (G - 1);
    const int s     = tid / G;
    const int b     = idx % BT;
    const int o     = idx / BT;

    const float cs = tau_scale(taup, tau_floor);

    #pragma unroll
    for (int i = tid; i < BT * (IN / 4); i += T) {
        int bb = i / (IN / 4), kv = i - bb * (IN / 4);
        float4 v = *(const float4*)&h[(bbase + bb) * IN + kv * 4];
        float4 r; r.x = v.x * cs; r.y = v.y * cs; r.z = v.z * cs; r.w = v.w * cs;
        *(float4*)&ch[bb * INP + kv * 4] = r;
    }
    #pragma unroll
    for (int i = tid; i < OT * (IN / 4); i += T) {
        int oo = i / (IN / 4), kv = i - oo * (IN / 4);
        float4 v = *(const float4*)&W[(obase + oo) * IN + kv * 4];
        float4 r;
        r.x = leaky_clamp01(v.x); r.y = leaky_clamp01(v.y);
        r.z = leaky_clamp01(v.z); r.w = leaky_clamp01(v.w);
        *(float4*)&aw[oo * INP + kv * 4] = r;
    }
    __syncthreads();

    float num = 0.0f, den = 0.0f;
    const float* cp = &ch[b * INP + s * KR];
    const float* ap = &aw[o * INP + s * KR];
    #pragma unroll 4
    for (int k = 0; k < KR; k += 4) {
        float4 c = *(const float4*)&cp[k];
        float4 a = *(const float4*)&ap[k];
        float z;
        z = c.x * a.x; { float e = ex2f(z); den += e; num = fmaf(e, z, num); }
        z = c.y * a.y; { float e = ex2f(z); den += e; num = fmaf(e, z, num); }
        z = c.z * a.z; { float e = ex2f(z); den += e; num = fmaf(e, z, num); }
        z = c.w * a.w; { float e = ex2f(z); den += e; num = fmaf(e, z, num); }
    }

    rnum[tid] = num;
    rden[tid] = den;
    __syncthreads();
    if (s == 0) {
        #pragma unroll
        for (int ss = 1; ss < S; ss++) {
            num += rnum[idx + ss * G];
            den += rden[idx + ss * G];
        }
        out[(bbase + b) * out_dim + obase + o] = 1.0f - (num / den) / cs;
    }
}

extern "C" void kernel_launch(void* const* d_in, const int* in_sizes, int n_in,
                              void* d_out, int out_size) {
    // metadata order: x, W0, tau0, W1, tau1, W2, tau2, W3, tau3
    const float* x  = (const float*)d_in[0];
    const float* W0 = (const float*)d_in[1];
    const float* t0 = (const float*)d_in[2];
    const float* W1 = (const float*)d_in[3];
    const float* t1 = (const float*)d_in[4];
    const float* W2 = (const float*)d_in[5];
    const float* t2 = (const float*)d_in[6];
    const float* W3 = (const float*)d_in[7];
    const float* t3 = (const float*)d_in[8];
    float* out = (float*)d_out;

    float *h1, *h2, *h3;
    cudaGetSymbolAddress((void**)&h1, g_h1);
    cudaGetSymbolAddress((void**)&h2, g_h2);
    cudaGetSymbolAddress((void**)&h3, g_h3);

    // tau_floor = log(in-1) + log(0.95/0.05)
    const float L19 = 2.9444389791664403f;
    const float tf0 = logf(1023.0f) + L19;
    const float tf1 = logf(1023.0f) + L19;
    const float tf2 = logf(511.0f)  + L19;
    const float tf3 = logf(255.0f)  + L19;

    // L0: 1024->1024, fused concat. 512 blocks x 128 thr, ~5 CTA/SM
    layer_chunked<1024, 8, 32, 256, true>
        <<<dim3(1024 / 32, B / 8), 128>>>(x, W0, t0, tf0, h1, 1024);
    // L1: 1024->512. 256 blocks x 128 thr
    layer_chunked<1024, 8, 32, 256, false>
        <<<dim3(512 / 32, B / 8), 128>>>(h1, W1, t1, tf1, h2, 512);
    // L2: 512->256, 4-way K split. 512 blocks x 256 thr
    layer_split<512, 8, 8, 4>
        <<<dim3(256 / 8, B / 8), 256>>>(h2, W2, t2, tf2, h3, 256);
    // L3: 256->128, 4-way K split. 256 blocks x 256 thr
    layer_split<256, 8, 8, 4>
        <<<dim3(128 / 8, B / 8), 256>>>(h3, W3, t3, tf3, out, 128);
}